// round 8
// baseline (speedup 1.0000x reference)
#include <cuda_runtime.h>
#include <cuda_bf16.h>
#include <cstdint>

// ---------------- problem dims ----------------
#define B_   64
#define NIN  2048
#define H_   1024
#define NOUT 2
#define T_   128
#define M_   (B_ * T_)          // 8192 time-batched rows

__device__ __constant__ float CD = (float)(1.0 - 0.3);
__device__ __constant__ float VD = (float)(1.0 - 0.8);
#define THRESH 1.0f

// ---------------- scratch ----------------
__device__ uint8_t g_A1[(size_t)M_ * NIN * 2];        // bf16 [M][NIN]
__device__ uint8_t g_A2[(size_t)M_ * H_ * 2];         // bf16 [M][H]
__device__ uint8_t g_W1s[(size_t)3 * H_ * NIN * 2];   // bf16 [sp][H][NIN]
__device__ uint8_t g_W2s[(size_t)3 * H_ * H_ * 2];    // bf16 [sp][H][H]
__device__ float   g_Z [(size_t)M_ * H_];             // fp32 pre-activation
__device__ float   g_S2[(size_t)M_ * H_];             // fp32 layer-2 spikes
__device__ float   g_Z3[(size_t)M_ * NOUT];

// ---------------- PTX helpers (base ISA only) ----------------
__device__ __forceinline__ uint32_t smem_u32(const void* p) {
    uint32_t a;
    asm("{ .reg .u64 t; cvta.to.shared.u64 t, %1; cvt.u32.u64 %0, t; }" : "=r"(a) : "l"(p));
    return a;
}
__device__ __forceinline__ void cpasync16(uint32_t dst, const void* src) {
    asm volatile("cp.async.cg.shared.global [%0], [%1], 16;" :: "r"(dst), "l"(src));
}
#define CP_COMMIT() asm volatile("cp.async.commit_group;" ::: "memory")
#define CP_WAIT1()  asm volatile("cp.async.wait_group 1;" ::: "memory")

__device__ __forceinline__ void ldsm_x4(uint32_t (&r)[4], uint32_t addr) {
    asm volatile("ldmatrix.sync.aligned.m8n8.x4.shared.b16 {%0,%1,%2,%3}, [%4];"
        : "=r"(r[0]), "=r"(r[1]), "=r"(r[2]), "=r"(r[3]) : "r"(addr));
}
__device__ __forceinline__ void mma16816(float (&d)[4], const uint32_t (&a)[4],
                                         uint32_t b0, uint32_t b1) {
    asm volatile(
        "mma.sync.aligned.m16n8k16.row.col.f32.bf16.bf16.f32 "
        "{%0,%1,%2,%3}, {%4,%5,%6,%7}, {%8,%9}, {%0,%1,%2,%3};"
        : "+f"(d[0]), "+f"(d[1]), "+f"(d[2]), "+f"(d[3])
        : "r"(a[0]), "r"(a[1]), "r"(a[2]), "r"(a[3]), "r"(b0), "r"(b1));
}

// ---------------- 1) transpose + convert: spike [B,I,T] -> A1 bf16 [m=(t*B+b)][i] ----------------
__global__ void transpose_spike(const float* __restrict__ in, __nv_bfloat16* __restrict__ a1) {
    __shared__ float tile[32][33];
    const int b  = blockIdx.z;
    const int i0 = blockIdx.y * 32;
    const int t0 = blockIdx.x * 32;
    const int tx = threadIdx.x, ty = threadIdx.y;   // 32 x 8
#pragma unroll
    for (int r = 0; r < 32; r += 8)
        tile[ty + r][tx] = in[((size_t)b * NIN + (i0 + ty + r)) * T_ + (t0 + tx)];
    __syncthreads();
#pragma unroll
    for (int r = 0; r < 32; r += 8) {
        const int t = t0 + ty + r;
        const int i = i0 + tx;
        const int m = t * B_ + b;
        a1[(size_t)m * NIN + i] = __float2bfloat16(tile[tx][ty + r]);
    }
}

// ---------------- 2) weight 3-way bf16 split -> [sp][n][K] ----------------
__global__ void wsplit(const float* __restrict__ W, __nv_bfloat16* __restrict__ out, int K) {
    const int ng  = K / 8;
    const int idx = blockIdx.x * blockDim.x + threadIdx.x;
    if (idx >= H_ * ng) return;
    const int n = idx / ng, k0 = (idx % ng) * 8;
    union { __nv_bfloat16 h[8]; uint4 v; } p1, p2, p3;
#pragma unroll
    for (int j = 0; j < 8; j++) {
        float w = W[(size_t)n * K + k0 + j];
        __nv_bfloat16 h1 = __float2bfloat16(w);
        float r1 = w - __bfloat162float(h1);
        __nv_bfloat16 h2 = __float2bfloat16(r1);
        float r2 = r1 - __bfloat162float(h2);
        __nv_bfloat16 h3 = __float2bfloat16(r2);
        p1.h[j] = h1; p2.h[j] = h2; p3.h[j] = h3;
    }
    const size_t sz = (size_t)H_ * K;
    *(uint4*)&out[(size_t)0 * sz + (size_t)n * K + k0] = p1.v;
    *(uint4*)&out[(size_t)1 * sz + (size_t)n * K + k0] = p2.v;
    *(uint4*)&out[(size_t)2 * sz + (size_t)n * K + k0] = p3.v;
}

// ---------------- 3) HMMA GEMM: C[m,n] = sum_sp sum_k A[m,k]*Wsp[n,k] ----------------
// CTA: 128x128 tile, 8 warps (2x4, warp tile 64x32), K-stage 32, 2-stage cp.async,
// 2 CTAs/SM (smem 80KB, regs forced <=128).
#define ROWB 80                        // 32 bf16 (64B) + 16B pad: ldmatrix conflict-free
#define TILE_BYTES (128 * ROWB)        // 10240
#define STG_BYTES  (4 * TILE_BYTES)    // A + 3 W splits = 40960
#define NSTG 2
#define GEMM_SMEM (NSTG * STG_BYTES)   // 81920

__device__ __forceinline__ void load_stage(uint32_t st, const uint8_t* __restrict__ Ab,
                                           const uint8_t* __restrict__ Wb,
                                           int bm, int bn, int c, int K, int tid) {
    const size_t krow = (size_t)K * 2;           // bytes per gmem row
    const size_t koff = (size_t)c * 64;          // this K-chunk's byte offset
#pragma unroll
    for (int i = 0; i < 2; i++) {
        const int idx = i * 256 + tid;
        const int row = idx >> 2, ch = idx & 3;
        cpasync16(st + row * ROWB + ch * 16,
                  Ab + (size_t)(bm + row) * krow + koff + ch * 16);
    }
#pragma unroll
    for (int sp = 0; sp < 3; sp++) {
#pragma unroll
        for (int i = 0; i < 2; i++) {
            const int idx = i * 256 + tid;
            const int row = idx >> 2, ch = idx & 3;
            cpasync16(st + (sp + 1) * TILE_BYTES + row * ROWB + ch * 16,
                      Wb + ((size_t)sp * H_ + bn + row) * krow + koff + ch * 16);
        }
    }
}

__global__ __launch_bounds__(256, 2)
void hmma_gemm(const uint8_t* __restrict__ Ab, const uint8_t* __restrict__ Wb,
               float* __restrict__ C, int K) {
    extern __shared__ uint8_t smem[];
    const uint32_t sb = smem_u32(smem);
    const int tid = threadIdx.x, lane = tid & 31, wid = tid >> 5;
    const int wm = wid >> 2, wn = wid & 3;       // 2 x 4 warp grid
    const int bm = blockIdx.y * 128, bn = blockIdx.x * 128;
    const int nch = K / 32;

    float acc[4][4][4];
#pragma unroll
    for (int i = 0; i < 4; i++)
#pragma unroll
        for (int j = 0; j < 4; j++)
#pragma unroll
            for (int v = 0; v < 4; v++) acc[i][j][v] = 0.f;

    load_stage(sb,             Ab, Wb, bm, bn, 0, K, tid); CP_COMMIT();
    load_stage(sb + STG_BYTES, Ab, Wb, bm, bn, 1, K, tid); CP_COMMIT();

    const int r16  = lane & 15;                  // ldmatrix row
    const int hb16 = (lane >> 4) << 4;           // ldmatrix 16B column half

    for (int c = 0; c < nch; c++) {
        CP_WAIT1();                              // stage c landed (c+1 may be in flight)
        __syncthreads();
        const uint32_t stage = sb + (c & 1) * STG_BYTES;
#pragma unroll
        for (int s = 0; s < 2; s++) {            // 2 x k16 steps
            uint32_t a[4][4];
#pragma unroll
            for (int i = 0; i < 4; i++)
                ldsm_x4(a[i], stage + (wm * 64 + i * 16 + r16) * ROWB + s * 32 + hb16);
#pragma unroll
            for (int sp = 0; sp < 3; sp++) {
                uint32_t b[2][4];
                const uint32_t bs = stage + (sp + 1) * TILE_BYTES;
#pragma unroll
                for (int j = 0; j < 2; j++)
                    ldsm_x4(b[j], bs + (wn * 32 + j * 16 + r16) * ROWB + s * 32 + hb16);
#pragma unroll
                for (int i = 0; i < 4; i++)
#pragma unroll
                    for (int nt = 0; nt < 4; nt++)
                        mma16816(acc[i][nt], a[i],
                                 b[nt >> 1][(nt & 1)], b[nt >> 1][(nt & 1) + 2]);
            }
        }
        __syncthreads();                         // all warps done reading stage c
        if (c + 2 < nch) load_stage(stage, Ab, Wb, bm, bn, c + 2, K, tid);
        CP_COMMIT();
    }

    // epilogue: mma d-frag -> C fp32 [M][1024]
    const int rr = lane >> 2, cc = (lane & 3) * 2;
#pragma unroll
    for (int i = 0; i < 4; i++) {
        const int row = bm + wm * 64 + i * 16 + rr;
#pragma unroll
        for (int nt = 0; nt < 4; nt++) {
            const int col = bn + wn * 32 + nt * 8 + cc;
            *(float2*)&C[(size_t)row * H_ + col]       = make_float2(acc[i][nt][0], acc[i][nt][1]);
            *(float2*)&C[(size_t)(row + 8) * H_ + col] = make_float2(acc[i][nt][2], acc[i][nt][3]);
        }
    }
}

// ---------------- 4) scans ----------------
__global__ void scan_bf16(const float* __restrict__ Z, __nv_bfloat16* __restrict__ a2) {
    const int n = blockIdx.x * blockDim.x + threadIdx.x;   // n = b*H + o
    if (n >= B_ * H_) return;
    const int b = n >> 10, o = n & 1023;
    const __nv_bfloat16 ONE = __float2bfloat16(1.0f);
    const __nv_bfloat16 ZER = __float2bfloat16(0.0f);
    float cur = 0.f, vol = 0.f;
    const float cd = CD, vd = VD;
    for (int t = 0; t < T_; t++) {
        const float z = Z[(size_t)t * (B_ * H_) + n];
        cur = cur * cd + z;
        vol = vol * vd + cur;
        const bool s = (vol - THRESH >= 0.f);
        vol = s ? 0.f : vol;
        a2[(size_t)(t * B_ + b) * H_ + o] = s ? ONE : ZER;
    }
}

__global__ void scan_f32(const float* __restrict__ Z, float* __restrict__ S, int Nn) {
    const int n = blockIdx.x * blockDim.x + threadIdx.x;
    if (n >= Nn) return;
    float cur = 0.f, vol = 0.f;
    const float cd = CD, vd = VD;
#pragma unroll 4
    for (int t = 0; t < T_; t++) {
        const float z = Z[(size_t)t * Nn + n];
        cur = cur * cd + z;
        vol = vol * vd + cur;
        const float s = (vol - THRESH >= 0.f) ? 1.f : 0.f;
        vol = (s > 0.f) ? 0.f : vol;
        S[(size_t)t * Nn + n] = s;
    }
}

// ---------------- 5) layer-3 GEMM (N=2): one warp per row ----------------
__global__ void gemm3_kernel(const float* __restrict__ S2, const float* __restrict__ W3,
                             float* __restrict__ Z3) {
    const int warp = (blockIdx.x * blockDim.x + threadIdx.x) >> 5;
    const int lane = threadIdx.x & 31;
    if (warp >= M_) return;
    const float* s = S2 + (size_t)warp * H_;
    float a0 = 0.f, a1 = 0.f;
#pragma unroll 8
    for (int k = lane; k < H_; k += 32) {
        const float sv = s[k];
        a0 += sv * W3[k];
        a1 += sv * W3[H_ + k];
    }
#pragma unroll
    for (int off = 16; off; off >>= 1) {
        a0 += __shfl_xor_sync(0xFFFFFFFFu, a0, off);
        a1 += __shfl_xor_sync(0xFFFFFFFFu, a1, off);
    }
    if (lane == 0) { Z3[(size_t)warp * 2] = a0; Z3[(size_t)warp * 2 + 1] = a1; }
}

// ---------------- 6) layer-3 scan + final output [B, 2, T] ----------------
__global__ void scan3_kernel(const float* __restrict__ Z3, float* __restrict__ out) {
    const int n = threadIdx.x;
    const int b = n >> 1, o = n & 1;
    float cur = 0.f, vol = 0.f;
    const float cd = CD, vd = VD;
    for (int t = 0; t < T_; t++) {
        const float z = Z3[t * (B_ * NOUT) + n];
        cur = cur * cd + z;
        vol = vol * vd + cur;
        const float s = (vol - THRESH >= 0.f) ? 1.f : 0.f;
        vol = (s > 0.f) ? 0.f : vol;
        out[((size_t)b * NOUT + o) * T_ + t] = s;
    }
}

// ---------------- launch ----------------
extern "C" void kernel_launch(void* const* d_in, const int* in_sizes, int n_in,
                              void* d_out, int out_size) {
    const float* spike = (const float*)d_in[0];   // [B, NIN, T]
    const float* W1    = (const float*)d_in[1];   // [H, NIN]
    const float* W2    = (const float*)d_in[2];   // [H, H]
    const float* W3    = (const float*)d_in[3];   // [NOUT, H]
    float* out = (float*)d_out;

    uint8_t *A1, *A2, *W1s, *W2s;
    float *Z, *S2, *Z3;
    cudaGetSymbolAddress((void**)&A1,  g_A1);
    cudaGetSymbolAddress((void**)&A2,  g_A2);
    cudaGetSymbolAddress((void**)&W1s, g_W1s);
    cudaGetSymbolAddress((void**)&W2s, g_W2s);
    cudaGetSymbolAddress((void**)&Z,   g_Z);
    cudaGetSymbolAddress((void**)&S2,  g_S2);
    cudaGetSymbolAddress((void**)&Z3,  g_Z3);

    cudaFuncSetAttribute(hmma_gemm, cudaFuncAttributeMaxDynamicSharedMemorySize, GEMM_SMEM);

    // 1) input spikes -> A1 (bf16 [M][NIN])
    {
        dim3 blk(32, 8), grd(T_ / 32, NIN / 32, B_);
        transpose_spike<<<grd, blk>>>(spike, (__nv_bfloat16*)A1);
    }
    // 2) weight splits
    wsplit<<<(H_ * (NIN / 8) + 255) / 256, 256>>>(W1, (__nv_bfloat16*)W1s, NIN);
    wsplit<<<(H_ * (H_  / 8) + 255) / 256, 256>>>(W2, (__nv_bfloat16*)W2s, H_);
    // 3) layer-1 GEMM (HMMA)
    {
        dim3 grd(H_ / 128, M_ / 128);
        hmma_gemm<<<grd, 256, GEMM_SMEM>>>(A1, W1s, Z, NIN);
    }
    // 4) layer-1 scan -> A2 (bf16)
    scan_bf16<<<(B_ * H_) / 256, 256>>>(Z, (__nv_bfloat16*)A2);
    // 5) layer-2 GEMM (HMMA)
    {
        dim3 grd(H_ / 128, M_ / 128);
        hmma_gemm<<<grd, 256, GEMM_SMEM>>>(A2, W2s, Z, H_);
    }
    // 6) layer-2 scan -> S2 (fp32)
    scan_f32<<<(B_ * H_) / 256, 256>>>(Z, S2, B_ * H_);
    // 7) layer-3
    gemm3_kernel<<<(M_ * 32) / 256, 256>>>(S2, W3, Z3);
    scan3_kernel<<<1, B_ * NOUT>>>(Z3, out);
}

// round 11
// speedup vs baseline: 1.3501x; 1.3501x over previous
#include <cuda_runtime.h>
#include <cuda_fp16.h>
#include <cstdint>

// ---------------- problem dims ----------------
#define B_   64
#define NIN  2048
#define H_   1024
#define NOUT 2
#define T_   128
#define M_   (B_ * T_)          // 8192 time-batched rows

__device__ __constant__ float CD = (float)(1.0 - 0.3);
__device__ __constant__ float VD = (float)(1.0 - 0.8);
#define THRESH 1.0f

// ---------------- scratch ----------------
__device__ uint8_t g_A1[(size_t)M_ * NIN * 2];        // fp16 [M][NIN]
__device__ uint8_t g_A2[(size_t)M_ * H_ * 2];         // fp16 [M][H]
__device__ uint8_t g_W1s[(size_t)2 * H_ * NIN * 2];   // fp16 [sp][H][NIN]
__device__ uint8_t g_W2s[(size_t)2 * H_ * H_ * 2];    // fp16 [sp][H][H]
__device__ float   g_Z [(size_t)M_ * H_];             // fp32 pre-activation
__device__ float   g_S2[(size_t)M_ * H_];             // fp32 layer-2 spikes
__device__ float   g_Z3[(size_t)M_ * NOUT];

// ---------------- PTX helpers (base ISA only) ----------------
__device__ __forceinline__ uint32_t smem_u32(const void* p) {
    uint32_t a;
    asm("{ .reg .u64 t; cvta.to.shared.u64 t, %1; cvt.u32.u64 %0, t; }" : "=r"(a) : "l"(p));
    return a;
}
__device__ __forceinline__ void cpasync16(uint32_t dst, const void* src) {
    asm volatile("cp.async.cg.shared.global [%0], [%1], 16;" :: "r"(dst), "l"(src));
}
#define CP_COMMIT() asm volatile("cp.async.commit_group;" ::: "memory")
#define CP_WAIT1()  asm volatile("cp.async.wait_group 1;" ::: "memory")

__device__ __forceinline__ void ldsm_x4(uint32_t (&r)[4], uint32_t addr) {
    asm volatile("ldmatrix.sync.aligned.m8n8.x4.shared.b16 {%0,%1,%2,%3}, [%4];"
        : "=r"(r[0]), "=r"(r[1]), "=r"(r[2]), "=r"(r[3]) : "r"(addr));
}
__device__ __forceinline__ void mma16816(float (&d)[4], const uint32_t (&a)[4],
                                         uint32_t b0, uint32_t b1) {
    asm volatile(
        "mma.sync.aligned.m16n8k16.row.col.f32.f16.f16.f32 "
        "{%0,%1,%2,%3}, {%4,%5,%6,%7}, {%8,%9}, {%0,%1,%2,%3};"
        : "+f"(d[0]), "+f"(d[1]), "+f"(d[2]), "+f"(d[3])
        : "r"(a[0]), "r"(a[1]), "r"(a[2]), "r"(a[3]), "r"(b0), "r"(b1));
}

// ---------------- 1) transpose + convert: spike [B,I,T] -> A1 fp16 [m=(t*B+b)][i] ----------------
__global__ void transpose_spike(const float* __restrict__ in, __half* __restrict__ a1) {
    __shared__ float tile[32][33];
    const int b  = blockIdx.z;
    const int i0 = blockIdx.y * 32;
    const int t0 = blockIdx.x * 32;
    const int tx = threadIdx.x, ty = threadIdx.y;   // 32 x 8
#pragma unroll
    for (int r = 0; r < 32; r += 8)
        tile[ty + r][tx] = in[((size_t)b * NIN + (i0 + ty + r)) * T_ + (t0 + tx)];
    __syncthreads();
#pragma unroll
    for (int r = 0; r < 32; r += 8) {
        const int t = t0 + ty + r;
        const int i = i0 + tx;
        const int m = t * B_ + b;
        a1[(size_t)m * NIN + i] = __float2half(tile[tx][ty + r]);
    }
}

// ---------------- 2) weight 2-way fp16 split (Dekker) -> [sp][n][K] ----------------
__global__ void wsplit(const float* __restrict__ W, __half* __restrict__ out, int K) {
    const int ng  = K / 8;
    const int idx = blockIdx.x * blockDim.x + threadIdx.x;
    if (idx >= H_ * ng) return;
    const int n = idx / ng, k0 = (idx % ng) * 8;
    union { __half h[8]; uint4 v; } p1, p2;
#pragma unroll
    for (int j = 0; j < 8; j++) {
        float w = W[(size_t)n * K + k0 + j];
        __half h1 = __float2half(w);
        float r1 = w - __half2float(h1);
        __half h2 = __float2half(r1);
        p1.h[j] = h1; p2.h[j] = h2;
    }
    const size_t sz = (size_t)H_ * K;
    *(uint4*)&out[(size_t)0 * sz + (size_t)n * K + k0] = p1.v;
    *(uint4*)&out[(size_t)1 * sz + (size_t)n * K + k0] = p2.v;
}

// ---------------- 3) HMMA GEMM: C[m,n] = sum_sp sum_k A[m,k]*Wsp[n,k] ----------------
// CTA: 128x128 tile, 8 warps (2x4, warp tile 64x32), K-stage 32, 2-stage cp.async,
// 2 CTAs/SM (smem 60KB, regs <=128).
#define ROWB 80                        // 32 fp16 (64B) + 16B pad: ldmatrix conflict-free
#define TILE_BYTES (128 * ROWB)        // 10240
#define STG_BYTES  (3 * TILE_BYTES)    // A + 2 W splits = 30720
#define NSTG 2
#define GEMM_SMEM (NSTG * STG_BYTES)   // 61440

__device__ __forceinline__ void load_stage(uint32_t st, const uint8_t* __restrict__ Ab,
                                           const uint8_t* __restrict__ Wb,
                                           int bm, int bn, int c, int K, int tid) {
    const size_t krow = (size_t)K * 2;           // bytes per gmem row
    const size_t koff = (size_t)c * 64;          // this K-chunk's byte offset
#pragma unroll
    for (int i = 0; i < 2; i++) {
        const int idx = i * 256 + tid;
        const int row = idx >> 2, ch = idx & 3;
        cpasync16(st + row * ROWB + ch * 16,
                  Ab + (size_t)(bm + row) * krow + koff + ch * 16);
    }
#pragma unroll
    for (int sp = 0; sp < 2; sp++) {
#pragma unroll
        for (int i = 0; i < 2; i++) {
            const int idx = i * 256 + tid;
            const int row = idx >> 2, ch = idx & 3;
            cpasync16(st + (sp + 1) * TILE_BYTES + row * ROWB + ch * 16,
                      Wb + ((size_t)sp * H_ + bn + row) * krow + koff + ch * 16);
        }
    }
}

__global__ __launch_bounds__(256, 2)
void hmma_gemm(const uint8_t* __restrict__ Ab, const uint8_t* __restrict__ Wb,
               float* __restrict__ C, int K) {
    extern __shared__ uint8_t smem[];
    const uint32_t sb = smem_u32(smem);
    const int tid = threadIdx.x, lane = tid & 31, wid = tid >> 5;
    const int wm = wid >> 2, wn = wid & 3;       // 2 x 4 warp grid
    const int bm = blockIdx.y * 128, bn = blockIdx.x * 128;
    const int nch = K / 32;

    float acc[4][4][4];
#pragma unroll
    for (int i = 0; i < 4; i++)
#pragma unroll
        for (int j = 0; j < 4; j++)
#pragma unroll
            for (int v = 0; v < 4; v++) acc[i][j][v] = 0.f;

    load_stage(sb,             Ab, Wb, bm, bn, 0, K, tid); CP_COMMIT();
    load_stage(sb + STG_BYTES, Ab, Wb, bm, bn, 1, K, tid); CP_COMMIT();

    const int r16  = lane & 15;                  // ldmatrix row
    const int hb16 = (lane >> 4) << 4;           // ldmatrix 16B column half

    for (int c = 0; c < nch; c++) {
        CP_WAIT1();                              // stage c landed (c+1 may be in flight)
        __syncthreads();
        const uint32_t stage = sb + (c & 1) * STG_BYTES;
#pragma unroll
        for (int s = 0; s < 2; s++) {            // 2 x k16 steps
            uint32_t a[4][4];
#pragma unroll
            for (int i = 0; i < 4; i++)
                ldsm_x4(a[i], stage + (wm * 64 + i * 16 + r16) * ROWB + s * 32 + hb16);
#pragma unroll
            for (int sp = 0; sp < 2; sp++) {
                uint32_t b[2][4];
                const uint32_t bs = stage + (sp + 1) * TILE_BYTES;
#pragma unroll
                for (int j = 0; j < 2; j++)
                    ldsm_x4(b[j], bs + (wn * 32 + j * 16 + r16) * ROWB + s * 32 + hb16);
#pragma unroll
                for (int i = 0; i < 4; i++)
#pragma unroll
                    for (int nt = 0; nt < 4; nt++)
                        mma16816(acc[i][nt], a[i],
                                 b[nt >> 1][(nt & 1)], b[nt >> 1][(nt & 1) + 2]);
            }
        }
        __syncthreads();                         // all warps done reading stage c
        if (c + 2 < nch) load_stage(stage, Ab, Wb, bm, bn, c + 2, K, tid);
        CP_COMMIT();
    }

    // epilogue: mma d-frag -> C fp32 [M][1024]
    const int rr = lane >> 2, cc = (lane & 3) * 2;
#pragma unroll
    for (int i = 0; i < 4; i++) {
        const int row = bm + wm * 64 + i * 16 + rr;
#pragma unroll
        for (int nt = 0; nt < 4; nt++) {
            const int col = bn + wn * 32 + nt * 8 + cc;
            *(float2*)&C[(size_t)row * H_ + col]       = make_float2(acc[i][nt][0], acc[i][nt][1]);
            *(float2*)&C[(size_t)(row + 8) * H_ + col] = make_float2(acc[i][nt][2], acc[i][nt][3]);
        }
    }
}

// ---------------- 4) scans ----------------
__global__ void scan_f16(const float* __restrict__ Z, __half* __restrict__ a2) {
    const int n = blockIdx.x * blockDim.x + threadIdx.x;   // n = b*H + o
    if (n >= B_ * H_) return;
    const int b = n >> 10, o = n & 1023;
    const __half ONE = __float2half(1.0f);
    const __half ZER = __float2half(0.0f);
    float cur = 0.f, vol = 0.f;
    const float cd = CD, vd = VD;
    for (int t = 0; t < T_; t++) {
        const float z = Z[(size_t)t * (B_ * H_) + n];
        cur = cur * cd + z;
        vol = vol * vd + cur;
        const bool s = (vol - THRESH >= 0.f);
        vol = s ? 0.f : vol;
        a2[(size_t)(t * B_ + b) * H_ + o] = s ? ONE : ZER;
    }
}

__global__ void scan_f32(const float* __restrict__ Z, float* __restrict__ S, int Nn) {
    const int n = blockIdx.x * blockDim.x + threadIdx.x;
    if (n >= Nn) return;
    float cur = 0.f, vol = 0.f;
    const float cd = CD, vd = VD;
#pragma unroll 4
    for (int t = 0; t < T_; t++) {
        const float z = Z[(size_t)t * Nn + n];
        cur = cur * cd + z;
        vol = vol * vd + cur;
        const float s = (vol - THRESH >= 0.f) ? 1.f : 0.f;
        vol = (s > 0.f) ? 0.f : vol;
        S[(size_t)t * Nn + n] = s;
    }
}

// ---------------- 5) layer-3 GEMM (N=2): one warp per row ----------------
__global__ void gemm3_kernel(const float* __restrict__ S2, const float* __restrict__ W3,
                             float* __restrict__ Z3) {
    const int warp = (blockIdx.x * blockDim.x + threadIdx.x) >> 5;
    const int lane = threadIdx.x & 31;
    if (warp >= M_) return;
    const float* s = S2 + (size_t)warp * H_;
    float a0 = 0.f, a1 = 0.f;
#pragma unroll 8
    for (int k = lane; k < H_; k += 32) {
        const float sv = s[k];
        a0 += sv * W3[k];
        a1 += sv * W3[H_ + k];
    }
#pragma unroll
    for (int off = 16; off; off >>= 1) {
        a0 += __shfl_xor_sync(0xFFFFFFFFu, a0, off);
        a1 += __shfl_xor_sync(0xFFFFFFFFu, a1, off);
    }
    if (lane == 0) { Z3[(size_t)warp * 2] = a0; Z3[(size_t)warp * 2 + 1] = a1; }
}

// ---------------- 6) layer-3 scan + final output [B, 2, T] ----------------
__global__ void scan3_kernel(const float* __restrict__ Z3, float* __restrict__ out) {
    const int n = threadIdx.x;
    const int b = n >> 1, o = n & 1;
    float cur = 0.f, vol = 0.f;
    const float cd = CD, vd = VD;
    for (int t = 0; t < T_; t++) {
        const float z = Z3[t * (B_ * NOUT) + n];
        cur = cur * cd + z;
        vol = vol * vd + cur;
        const float s = (vol - THRESH >= 0.f) ? 1.f : 0.f;
        vol = (s > 0.f) ? 0.f : vol;
        out[((size_t)b * NOUT + o) * T_ + t] = s;
    }
}

// ---------------- launch ----------------
extern "C" void kernel_launch(void* const* d_in, const int* in_sizes, int n_in,
                              void* d_out, int out_size) {
    const float* spike = (const float*)d_in[0];   // [B, NIN, T]
    const float* W1    = (const float*)d_in[1];   // [H, NIN]
    const float* W2    = (const float*)d_in[2];   // [H, H]
    const float* W3    = (const float*)d_in[3];   // [NOUT, H]
    float* out = (float*)d_out;

    uint8_t *A1, *A2, *W1s, *W2s;
    float *Z, *S2, *Z3;
    cudaGetSymbolAddress((void**)&A1,  g_A1);
    cudaGetSymbolAddress((void**)&A2,  g_A2);
    cudaGetSymbolAddress((void**)&W1s, g_W1s);
    cudaGetSymbolAddress((void**)&W2s, g_W2s);
    cudaGetSymbolAddress((void**)&Z,   g_Z);
    cudaGetSymbolAddress((void**)&S2,  g_S2);
    cudaGetSymbolAddress((void**)&Z3,  g_Z3);

    cudaFuncSetAttribute(hmma_gemm, cudaFuncAttributeMaxDynamicSharedMemorySize, GEMM_SMEM);

    // 1) input spikes -> A1 (fp16 [M][NIN])
    {
        dim3 blk(32, 8), grd(T_ / 32, NIN / 32, B_);
        transpose_spike<<<grd, blk>>>(spike, (__half*)A1);
    }
    // 2) weight splits (fp16 Dekker 2-way)
    wsplit<<<(H_ * (NIN / 8) + 255) / 256, 256>>>(W1, (__half*)W1s, NIN);
    wsplit<<<(H_ * (H_  / 8) + 255) / 256, 256>>>(W2, (__half*)W2s, H_);
    // 3) layer-1 GEMM (HMMA)
    {
        dim3 grd(H_ / 128, M_ / 128);
        hmma_gemm<<<grd, 256, GEMM_SMEM>>>(A1, W1s, Z, NIN);
    }
    // 4) layer-1 scan -> A2 (fp16)
    scan_f16<<<(B_ * H_) / 256, 256>>>(Z, (__half*)A2);
    // 5) layer-2 GEMM (HMMA)
    {
        dim3 grd(H_ / 128, M_ / 128);
        hmma_gemm<<<grd, 256, GEMM_SMEM>>>(A2, W2s, Z, H_);
    }
    // 6) layer-2 scan -> S2 (fp32)
    scan_f32<<<(B_ * H_) / 256, 256>>>(Z, S2, B_ * H_);
    // 7) layer-3
    gemm3_kernel<<<(M_ * 32) / 256, 256>>>(S2, W3, Z3);
    scan3_kernel<<<1, B_ * NOUT>>>(Z3, out);
}